// round 1
// baseline (speedup 1.0000x reference)
#include <cuda_runtime.h>
#include <cuda_bf16.h>
#include <math.h>

#define D      256
#define KNBR   32
#define TOPK   16
#define MAXN   20000

// Scratch (allocation-free rule: __device__ globals)
__device__ float g_u[MAXN * D];     // weighted neighbor sums, [N, 256]
__device__ float g_vs[D];           // self_weights @ attention_weights
__device__ float g_vn[D];           // neigh_weights @ attention_weights

// ---------------------------------------------------------------------------
// Phase 0: v = W @ a   (two 256x256 GEMVs; block 0 -> self, block 1 -> neigh)
// ---------------------------------------------------------------------------
__global__ void __launch_bounds__(256)
phase0_kernel(const float* __restrict__ sw, const float* __restrict__ nw,
              const float* __restrict__ attn)
{
    __shared__ float a[D];
    int t = threadIdx.x;
    a[t] = attn[t];
    __syncthreads();

    const float* w = (blockIdx.x == 0) ? sw : nw;
    const float4* wr = (const float4*)(w + (size_t)t * D);
    float acc = 0.f;
#pragma unroll
    for (int i = 0; i < D / 4; i++) {
        float4 v = wr[i];
        acc += v.x * a[4 * i + 0] + v.y * a[4 * i + 1]
             + v.z * a[4 * i + 2] + v.w * a[4 * i + 3];
    }
    if (blockIdx.x == 0) g_vs[t] = acc; else g_vn[t] = acc;
}

// ---------------------------------------------------------------------------
// Phase 1: per node — load 32x256 neighbor tile to SMEM, logits via dot with
// v_n, softmax over 33 (incl. self), top-16 by rank, weighted sum -> g_u.
// ---------------------------------------------------------------------------
__global__ void __launch_bounds__(256)
phase1_kernel(const float* __restrict__ self_vecs,
              const float* __restrict__ neigh_vecs)
{
    __shared__ float4 tile[KNBR * D / 4];   // 32 KB: raw neighbor vectors
    __shared__ float4 vn4[D / 4];           // 1 KB: v_neigh
    __shared__ float  dots[KNBR];
    __shared__ float  warp_part[8];
    __shared__ float  s_selflogit;
    __shared__ float  sel_w[TOPK];
    __shared__ int    sel_i[TOPK];

    const int n    = blockIdx.x;
    const int t    = threadIdx.x;
    const int wid  = t >> 5;
    const int lane = t & 31;

    // Streaming load of this node's 32x256 tile (8 x float4 per thread)
    const float4* src = (const float4*)(neigh_vecs + (size_t)n * KNBR * D);
#pragma unroll
    for (int i = 0; i < 8; i++) tile[t + 256 * i] = src[t + 256 * i];
    if (t < D / 4) vn4[t] = ((const float4*)g_vn)[t];

    // Self logit partial: self_vecs[n] . v_self
    float sp = self_vecs[(size_t)n * D + t] * g_vs[t];
#pragma unroll
    for (int o = 16; o > 0; o >>= 1) sp += __shfl_down_sync(0xffffffffu, sp, o);
    if (lane == 0) warp_part[wid] = sp;
    __syncthreads();

    // Neighbor dots: warp w handles rows 4w..4w+3 (conflict-free float4 LDS)
#pragma unroll
    for (int r = 0; r < 4; r++) {
        int row = wid * 4 + r;
        float4 a0 = tile[row * 64 + lane];
        float4 a1 = tile[row * 64 + 32 + lane];
        float4 b0 = vn4[lane];
        float4 b1 = vn4[32 + lane];
        float p = a0.x * b0.x + a0.y * b0.y + a0.z * b0.z + a0.w * b0.w
                + a1.x * b1.x + a1.y * b1.y + a1.z * b1.z + a1.w * b1.w;
#pragma unroll
        for (int o = 16; o > 0; o >>= 1) p += __shfl_down_sync(0xffffffffu, p, o);
        if (lane == 0) dots[row] = p;
    }
    if (t == 0) {
        float s = 0.f;
#pragma unroll
        for (int i = 0; i < 8; i++) s += warp_part[i];
        s_selflogit = s;
    }
    __syncthreads();

    // Warp 0: relu -> softmax over 33 -> rank -> select top-16
    if (wid == 0) {
        float l  = fmaxf(dots[lane], 0.f);       // neighbor logit (one per lane)
        float l0 = fmaxf(s_selflogit, 0.f);      // self logit
        float m = l;
#pragma unroll
        for (int o = 16; o > 0; o >>= 1) m = fmaxf(m, __shfl_xor_sync(0xffffffffu, m, o));
        m = fmaxf(m, l0);
        float e = expf(l - m);
        float ssum = e;
#pragma unroll
        for (int o = 16; o > 0; o >>= 1) ssum += __shfl_xor_sync(0xffffffffu, ssum, o);
        float denom = ssum + expf(l0 - m);
        float score = e / denom;                 // neighbor softmax weight

        // rank among 32 neighbor scores; ties -> lower index first (JAX top_k)
        int rank = 0;
#pragma unroll
        for (int j = 0; j < KNBR; j++) {
            float sj = __shfl_sync(0xffffffffu, score, j);
            rank += (sj > score) || (sj == score && j < lane);
        }
        if (rank < TOPK) { sel_w[rank] = score; sel_i[rank] = lane; }
    }
    __syncthreads();

    // Weighted sum of selected rows: thread t owns element d=t
    const float* ts = (const float*)tile;
    float acc = 0.f;
#pragma unroll
    for (int i = 0; i < TOPK; i++) acc += sel_w[i] * ts[sel_i[i] * D + t];
    g_u[(size_t)n * D + t] = acc;
}

// ---------------------------------------------------------------------------
// Phase 2: out = relu([self | u] @ [Ws ; Wn])  — K=512 fp32 SGEMM
// BM=128, BN=128, BK=16, 256 threads, 8x8 microtile
// ---------------------------------------------------------------------------
#define BM 128
#define BN 128
#define BK 16

__global__ void __launch_bounds__(256)
phase2_kernel(const float* __restrict__ self_vecs,
              const float* __restrict__ ws, const float* __restrict__ nw,
              float* __restrict__ out, int nrows)
{
    __shared__ float As[BK][BM + 4];
    __shared__ float Bs[BK][BN];

    const int t    = threadIdx.x;
    const int row0 = blockIdx.x * BM;
    const int col0 = blockIdx.y * BN;
    const int tx   = t & 15;
    const int ty   = t >> 4;

    float acc[8][8] = {};

    for (int kb = 0; kb < 2 * D; kb += BK) {
        // --- A tile: 128 rows x 16 k (2 float4 loads/thread, store transposed)
#pragma unroll
        for (int i = 0; i < 2; i++) {
            int idx = t + i * 256;          // 0..511
            int r   = idx >> 2;             // 0..127
            int c4  = idx & 3;              // float4 index within the 16-k row
            int grow = row0 + r;
            int gk   = kb + c4 * 4;
            float4 v = make_float4(0.f, 0.f, 0.f, 0.f);
            if (grow < nrows) {
                const float* base = (gk < D)
                    ? (self_vecs + (size_t)grow * D + gk)
                    : (g_u       + (size_t)grow * D + (gk - D));
                v = *(const float4*)base;
            }
            As[c4 * 4 + 0][r] = v.x;
            As[c4 * 4 + 1][r] = v.y;
            As[c4 * 4 + 2][r] = v.z;
            As[c4 * 4 + 3][r] = v.w;
        }
        // --- B tile: 16 k x 128 cols (weights; stays hot in L2)
#pragma unroll
        for (int i = 0; i < 2; i++) {
            int idx = t + i * 256;          // 0..511
            int r   = idx >> 5;             // 0..15
            int c4  = idx & 31;             // 0..31
            int gk  = kb + r;
            const float* wbase = (gk < D)
                ? (ws + (size_t)gk * D + col0 + c4 * 4)
                : (nw + (size_t)(gk - D) * D + col0 + c4 * 4);
            *(float4*)&Bs[r][c4 * 4] = *(const float4*)wbase;
        }
        __syncthreads();

#pragma unroll
        for (int kk = 0; kk < BK; kk++) {
            float a[8], b[8];
            *(float4*)&a[0] = *(float4*)&As[kk][ty * 8];
            *(float4*)&a[4] = *(float4*)&As[kk][ty * 8 + 4];
            *(float4*)&b[0] = *(float4*)&Bs[kk][tx * 8];
            *(float4*)&b[4] = *(float4*)&Bs[kk][tx * 8 + 4];
#pragma unroll
            for (int i = 0; i < 8; i++)
#pragma unroll
                for (int j = 0; j < 8; j++)
                    acc[i][j] += a[i] * b[j];
        }
        __syncthreads();
    }

    // relu + store
#pragma unroll
    for (int i = 0; i < 8; i++) {
        int r = row0 + ty * 8 + i;
        if (r >= nrows) break;
#pragma unroll
        for (int j = 0; j < 8; j += 4) {
            float4 v;
            v.x = fmaxf(acc[i][j + 0], 0.f);
            v.y = fmaxf(acc[i][j + 1], 0.f);
            v.z = fmaxf(acc[i][j + 2], 0.f);
            v.w = fmaxf(acc[i][j + 3], 0.f);
            *(float4*)&out[(size_t)r * D + col0 + tx * 8 + j] = v;
        }
    }
}

// ---------------------------------------------------------------------------
extern "C" void kernel_launch(void* const* d_in, const int* in_sizes, int n_in,
                              void* d_out, int out_size)
{
    const float* self_vecs = (const float*)d_in[0];
    const float* neigh     = (const float*)d_in[1];
    const float* sw        = (const float*)d_in[2];
    const float* nw        = (const float*)d_in[3];
    const float* attn      = (const float*)d_in[4];
    float* out             = (float*)d_out;

    const int nrows = in_sizes[0] / D;   // 20000

    phase0_kernel<<<2, 256>>>(sw, nw, attn);
    phase1_kernel<<<nrows, 256>>>(self_vecs, neigh);
    dim3 g2((nrows + BM - 1) / BM, D / BN);
    phase2_kernel<<<g2, 256>>>(self_vecs, sw, nw, out, nrows);
}

// round 3
// speedup vs baseline: 1.4859x; 1.4859x over previous
#include <cuda_runtime.h>
#include <cuda_bf16.h>
#include <math.h>
#include <stdint.h>

#define D      256
#define KNBR   32
#define TOPK   16
#define MAXN   20096      // 157 * 128, padded
#define K2     512        // GEMM K = 2*D

// ---------------- scratch (__device__ globals; zero-init, no allocs) -------
__device__ __align__(128) __nv_bfloat16 g_Ah[(size_t)MAXN * K2];  // [row, 512] hi
__device__ __align__(128) __nv_bfloat16 g_Al[(size_t)MAXN * K2];  // [row, 512] lo
__device__ __align__(128) __nv_bfloat16 g_Bh[D * K2];             // [n, 512] hi (W^T)
__device__ __align__(128) __nv_bfloat16 g_Bl[D * K2];             // [n, 512] lo
__device__ float g_vs[D];
__device__ float g_vn[D];

__device__ __forceinline__ uint32_t smem_u32(const void* p) {
    uint32_t a;
    asm("{ .reg .u64 t; cvta.to.shared.u64 t, %1; cvt.u32.u64 %0, t; }" : "=r"(a) : "l"(p));
    return a;
}

// ---------------------------------------------------------------------------
// Phase 0: v = W @ a   (grid (2,8): x = matrix, y = 32-row group; warp = 4 rows)
// ---------------------------------------------------------------------------
__global__ void __launch_bounds__(256)
phase0_kernel(const float* __restrict__ sw, const float* __restrict__ nw,
              const float* __restrict__ attn)
{
    __shared__ float a[D];
    const int t = threadIdx.x, wid = t >> 5, lane = t & 31;
    a[t] = attn[t];
    __syncthreads();

    const float* w = (blockIdx.x == 0) ? sw : nw;
#pragma unroll
    for (int r = 0; r < 4; r++) {
        int row = blockIdx.y * 32 + wid * 4 + r;
        const float4* wr = (const float4*)(w + (size_t)row * D);
        float4 v0 = wr[lane], v1 = wr[lane + 32];
        float p = v0.x * a[4 * lane + 0] + v0.y * a[4 * lane + 1]
                + v0.z * a[4 * lane + 2] + v0.w * a[4 * lane + 3]
                + v1.x * a[128 + 4 * lane + 0] + v1.y * a[128 + 4 * lane + 1]
                + v1.z * a[128 + 4 * lane + 2] + v1.w * a[128 + 4 * lane + 3];
#pragma unroll
        for (int o = 16; o > 0; o >>= 1) p += __shfl_down_sync(0xffffffffu, p, o);
        if (lane == 0) { if (blockIdx.x == 0) g_vs[row] = p; else g_vn[row] = p; }
    }
}

// ---------------------------------------------------------------------------
// convert B = [Ws ; Wn]^T to bf16 hi/lo:  B[n, k] = W[k, n]
// ---------------------------------------------------------------------------
__global__ void __launch_bounds__(256)
convB_kernel(const float* __restrict__ ws, const float* __restrict__ nw)
{
    int idx = blockIdx.x * 256 + threadIdx.x;       // 0 .. 131071
    int n = idx & 255;
    int k = idx >> 8;                                // 0 .. 511
    float w = (k < D) ? ws[(size_t)k * D + n] : nw[(size_t)(k - D) * D + n];
    __nv_bfloat16 h = __float2bfloat16(w);
    float lo = w - __bfloat162float(h);
    g_Bh[(size_t)n * K2 + k] = h;
    g_Bl[(size_t)n * K2 + k] = __float2bfloat16(lo);
}

// ---------------------------------------------------------------------------
// Phase 1: per node — logits, softmax over 33, top-16, weighted neighbor sum.
// Writes A = [self | u] directly as bf16 hi/lo.
// ---------------------------------------------------------------------------
__global__ void __launch_bounds__(256)
phase1_kernel(const float* __restrict__ self_vecs,
              const float* __restrict__ neigh_vecs)
{
    __shared__ float4 tile[KNBR * D / 4];   // 32 KB
    __shared__ float4 vn4[D / 4];
    __shared__ float  dots[KNBR];
    __shared__ float  warp_part[8];
    __shared__ float  s_selflogit;
    __shared__ float  sel_w[TOPK];
    __shared__ int    sel_i[TOPK];

    const int n    = blockIdx.x;
    const int t    = threadIdx.x;
    const int wid  = t >> 5;
    const int lane = t & 31;

    const float4* src = (const float4*)(neigh_vecs + (size_t)n * KNBR * D);
#pragma unroll
    for (int i = 0; i < 8; i++) tile[t + 256 * i] = src[t + 256 * i];
    if (t < D / 4) vn4[t] = ((const float4*)g_vn)[t];

    // self row element t: logit partial + bf16 hi/lo write (A columns 0..255)
    float sv = self_vecs[(size_t)n * D + t];
    {
        __nv_bfloat16 h = __float2bfloat16(sv);
        float lo = sv - __bfloat162float(h);
        g_Ah[(size_t)n * K2 + t] = h;
        g_Al[(size_t)n * K2 + t] = __float2bfloat16(lo);
    }
    float sp = sv * g_vs[t];
#pragma unroll
    for (int o = 16; o > 0; o >>= 1) sp += __shfl_down_sync(0xffffffffu, sp, o);
    if (lane == 0) warp_part[wid] = sp;
    __syncthreads();

#pragma unroll
    for (int r = 0; r < 4; r++) {
        int row = wid * 4 + r;
        float4 a0 = tile[row * 64 + lane];
        float4 a1 = tile[row * 64 + 32 + lane];
        float4 b0 = vn4[lane];
        float4 b1 = vn4[32 + lane];
        float p = a0.x * b0.x + a0.y * b0.y + a0.z * b0.z + a0.w * b0.w
                + a1.x * b1.x + a1.y * b1.y + a1.z * b1.z + a1.w * b1.w;
#pragma unroll
        for (int o = 16; o > 0; o >>= 1) p += __shfl_down_sync(0xffffffffu, p, o);
        if (lane == 0) dots[row] = p;
    }
    if (t == 0) {
        float s = 0.f;
#pragma unroll
        for (int i = 0; i < 8; i++) s += warp_part[i];
        s_selflogit = s;
    }
    __syncthreads();

    if (wid == 0) {
        float l  = fmaxf(dots[lane], 0.f);
        float l0 = fmaxf(s_selflogit, 0.f);
        float m = l;
#pragma unroll
        for (int o = 16; o > 0; o >>= 1) m = fmaxf(m, __shfl_xor_sync(0xffffffffu, m, o));
        m = fmaxf(m, l0);
        float e = expf(l - m);
        float ssum = e;
#pragma unroll
        for (int o = 16; o > 0; o >>= 1) ssum += __shfl_xor_sync(0xffffffffu, ssum, o);
        float denom = ssum + expf(l0 - m);
        float score = e / denom;

        int rank = 0;
#pragma unroll
        for (int j = 0; j < KNBR; j++) {
            float sj = __shfl_sync(0xffffffffu, score, j);
            rank += (sj > score) || (sj == score && j < lane);
        }
        if (rank < TOPK) { sel_w[rank] = score; sel_i[rank] = lane; }
    }
    __syncthreads();

    // weighted sum, element d = t -> A columns 256..511 as bf16 hi/lo
    const float* ts = (const float*)tile;
    float acc = 0.f;
#pragma unroll
    for (int i = 0; i < TOPK; i++) acc += sel_w[i] * ts[sel_i[i] * D + t];
    __nv_bfloat16 h = __float2bfloat16(acc);
    float lo = acc - __bfloat162float(h);
    g_Ah[(size_t)n * K2 + D + t] = h;
    g_Al[(size_t)n * K2 + D + t] = __float2bfloat16(lo);
}

// ---------------------------------------------------------------------------
// Phase 2: out = relu(A @ B^T), bf16-split via mma.sync (HMMA legacy path).
// BM=128, BN=128, BK=32, 8 warps (64x32 warp tiles), cp.async double buffer.
// ---------------------------------------------------------------------------
#define BK   32
#define RS   40                      // padded row stride in bf16 elems (80 B)
#define TILE_ELEMS (128 * RS)        // per tile (A or B), 10240 B

__global__ void __launch_bounds__(256)
gemm_kernel(float* __restrict__ out, int nrows)
{
    __shared__ __nv_bfloat16 smA[2][TILE_ELEMS];
    __shared__ __nv_bfloat16 smB[2][TILE_ELEMS];

    const int t    = threadIdx.x;
    const int wid  = t >> 5;
    const int lane = t & 31;
    const int row0 = blockIdx.x * 128;
    const int col0 = blockIdx.y * 128;
    const int wm   = (wid >> 2) * 64;    // warp m offset: 0 / 64
    const int wn   = (wid & 3) * 32;     // warp n offset: 0/32/64/96

    const int lr = t >> 2;               // load row 0..63? no: t/4 -> 0..63
    const int lc = t & 3;                // chunk 0..3 (8 bf16 each)

    float acc[4][4][4];
#pragma unroll
    for (int i = 0; i < 4; i++)
#pragma unroll
        for (int j = 0; j < 4; j++)
#pragma unroll
            for (int q = 0; q < 4; q++) acc[i][j][q] = 0.f;

    const int NIT = 48;                  // 3 passes x (512/32)

    // prefetch helper (macro-ish lambda): iteration -> pass/koff, cp.async both tiles
    auto prefetch = [&](int it, int buf) {
        const int pass = it >> 4;
        const int koff = (it & 15) * BK;
        const __nv_bfloat16* Ap = (pass == 2) ? g_Al : g_Ah;
        const __nv_bfloat16* Bp = (pass == 1) ? g_Bl : g_Bh;
        // 1024 chunks of 16B per tile; 4 per thread. rows: idx>>2, chunk: idx&3
#pragma unroll
        for (int i = 0; i < 2; i++) {
            int r = lr + i * 64;                 // 0..127
            uint32_t da = smem_u32(&smA[buf][r * RS + lc * 8]);
            const void* sa = Ap + (size_t)(row0 + r) * K2 + koff + lc * 8;
            asm volatile("cp.async.cg.shared.global [%0], [%1], 16;" :: "r"(da), "l"(sa));
            uint32_t db = smem_u32(&smB[buf][r * RS + lc * 8]);
            const void* sb = Bp + (size_t)(col0 + r) * K2 + koff + lc * 8;
            asm volatile("cp.async.cg.shared.global [%0], [%1], 16;" :: "r"(db), "l"(sb));
        }
        asm volatile("cp.async.commit_group;");
    };

    prefetch(0, 0);

#pragma unroll 1
    for (int it = 0; it < NIT; it++) {
        const int buf = it & 1;
        if (it + 1 < NIT) prefetch(it + 1, buf ^ 1);
        else asm volatile("cp.async.commit_group;");
        asm volatile("cp.async.wait_group 1;");
        __syncthreads();

#pragma unroll
        for (int s = 0; s < 2; s++) {            // two k16 steps in BK=32
            uint32_t a[4][4], b[4][2];
            // A fragments: 4 m-tiles, ldmatrix x4
#pragma unroll
            for (int i = 0; i < 4; i++) {
                int rowA = wm + i * 16 + (lane & 15);
                int ka   = s * 16 + ((lane >> 4) << 3);
                uint32_t ad = smem_u32(&smA[buf][rowA * RS + ka]);
                asm volatile("ldmatrix.sync.aligned.m8n8.x4.shared.b16 {%0,%1,%2,%3}, [%4];"
                             : "=r"(a[i][0]), "=r"(a[i][1]), "=r"(a[i][2]), "=r"(a[i][3])
                             : "r"(ad));
            }
            // B fragments: 4 n-tiles, ldmatrix x2 (lanes 0-15 supply addresses)
#pragma unroll
            for (int j = 0; j < 4; j++) {
                int rowB = wn + j * 8 + (lane & 7);
                int kb   = s * 16 + (((lane >> 3) & 1) << 3);
                uint32_t bd = smem_u32(&smB[buf][rowB * RS + kb]);
                asm volatile("ldmatrix.sync.aligned.m8n8.x2.shared.b16 {%0,%1}, [%2];"
                             : "=r"(b[j][0]), "=r"(b[j][1]) : "r"(bd));
            }
#pragma unroll
            for (int i = 0; i < 4; i++)
#pragma unroll
                for (int j = 0; j < 4; j++) {
                    asm volatile(
                        "mma.sync.aligned.m16n8k16.row.col.f32.bf16.bf16.f32 "
                        "{%0,%1,%2,%3}, {%4,%5,%6,%7}, {%8,%9}, {%0,%1,%2,%3};"
                        : "+f"(acc[i][j][0]), "+f"(acc[i][j][1]),
                          "+f"(acc[i][j][2]), "+f"(acc[i][j][3])
                        : "r"(a[i][0]), "r"(a[i][1]), "r"(a[i][2]), "r"(a[i][3]),
                          "r"(b[j][0]), "r"(b[j][1]));
                }
        }
        __syncthreads();
    }

    // epilogue: relu + store (float2 per half-tile-row)
#pragma unroll
    for (int i = 0; i < 4; i++) {
        int rA = row0 + wm + i * 16 + (lane >> 2);
        int rB = rA + 8;
#pragma unroll
        for (int j = 0; j < 4; j++) {
            int c = col0 + wn + j * 8 + (lane & 3) * 2;
            if (rA < nrows) {
                float2 v;
                v.x = fmaxf(acc[i][j][0], 0.f);
                v.y = fmaxf(acc[i][j][1], 0.f);
                *(float2*)&out[(size_t)rA * D + c] = v;
            }
            if (rB < nrows) {
                float2 v;
                v.x = fmaxf(acc[i][j][2], 0.f);
                v.y = fmaxf(acc[i][j][3], 0.f);
                *(float2*)&out[(size_t)rB * D + c] = v;
            }
        }
    }
}

// ---------------------------------------------------------------------------
extern "C" void kernel_launch(void* const* d_in, const int* in_sizes, int n_in,
                              void* d_out, int out_size)
{
    const float* self_vecs = (const float*)d_in[0];
    const float* neigh     = (const float*)d_in[1];
    const float* sw        = (const float*)d_in[2];
    const float* nw        = (const float*)d_in[3];
    const float* attn      = (const float*)d_in[4];
    float* out             = (float*)d_out;

    const int nrows = in_sizes[0] / D;   // 20000

    phase0_kernel<<<dim3(2, 8), 256>>>(sw, nw, attn);
    convB_kernel<<<(D * K2) / 256, 256>>>(sw, nw);
    phase1_kernel<<<nrows, 256>>>(self_vecs, neigh);

    dim3 g2((nrows + 127) / 128, 2);
    gemm_kernel<<<g2, 256>>>(out, nrows);
}

// round 4
// speedup vs baseline: 1.6577x; 1.1156x over previous
#include <cuda_runtime.h>
#include <cuda_bf16.h>
#include <math.h>
#include <stdint.h>

#define D      256
#define KNBR   32
#define TOPK   16
#define MAXN   20096      // 157 * 128, padded
#define K2     512        // GEMM K = 2*D

// ---------------- scratch (__device__ globals; zero-init, no allocs) -------
__device__ __align__(128) __nv_bfloat16 g_Ah[(size_t)MAXN * K2];  // [row, 512] hi
__device__ __align__(128) __nv_bfloat16 g_Al[(size_t)MAXN * K2];  // [row, 512] lo
__device__ __align__(128) __nv_bfloat16 g_Bh[D * K2];             // [n, 512] hi (W^T)
__device__ __align__(128) __nv_bfloat16 g_Bl[D * K2];             // [n, 512] lo
__device__ float g_vs[D];
__device__ float g_vn[D];

__device__ __forceinline__ uint32_t smem_u32(const void* p) {
    uint32_t a;
    asm("{ .reg .u64 t; cvta.to.shared.u64 t, %1; cvt.u32.u64 %0, t; }" : "=r"(a) : "l"(p));
    return a;
}

// ---------------------------------------------------------------------------
// Phase 0: v = W @ a
// ---------------------------------------------------------------------------
__global__ void __launch_bounds__(256)
phase0_kernel(const float* __restrict__ sw, const float* __restrict__ nw,
              const float* __restrict__ attn)
{
    __shared__ float a[D];
    const int t = threadIdx.x, wid = t >> 5, lane = t & 31;
    a[t] = attn[t];
    __syncthreads();

    const float* w = (blockIdx.x == 0) ? sw : nw;
#pragma unroll
    for (int r = 0; r < 4; r++) {
        int row = blockIdx.y * 32 + wid * 4 + r;
        const float4* wr = (const float4*)(w + (size_t)row * D);
        float4 v0 = wr[lane], v1 = wr[lane + 32];
        float p = v0.x * a[4 * lane + 0] + v0.y * a[4 * lane + 1]
                + v0.z * a[4 * lane + 2] + v0.w * a[4 * lane + 3]
                + v1.x * a[128 + 4 * lane + 0] + v1.y * a[128 + 4 * lane + 1]
                + v1.z * a[128 + 4 * lane + 2] + v1.w * a[128 + 4 * lane + 3];
#pragma unroll
        for (int o = 16; o > 0; o >>= 1) p += __shfl_down_sync(0xffffffffu, p, o);
        if (lane == 0) { if (blockIdx.x == 0) g_vs[row] = p; else g_vn[row] = p; }
    }
}

// ---------------------------------------------------------------------------
// convert B = [Ws ; Wn]^T to bf16 hi/lo:  B[n, k] = W[k, n]
// ---------------------------------------------------------------------------
__global__ void __launch_bounds__(256)
convB_kernel(const float* __restrict__ ws, const float* __restrict__ nw)
{
    int idx = blockIdx.x * 256 + threadIdx.x;       // 0 .. 131071
    int n = idx & 255;
    int k = idx >> 8;                                // 0 .. 511
    float w = (k < D) ? ws[(size_t)k * D + n] : nw[(size_t)(k - D) * D + n];
    __nv_bfloat16 h = __float2bfloat16(w);
    float lo = w - __bfloat162float(h);
    g_Bh[(size_t)n * K2 + k] = h;
    g_Bl[(size_t)n * K2 + k] = __float2bfloat16(lo);
}

// ---------------------------------------------------------------------------
// Phase 1: per node — logits, softmax over 33, top-16, weighted neighbor sum.
// Writes A = [self | u] directly as bf16 hi/lo.
// ---------------------------------------------------------------------------
__global__ void __launch_bounds__(256)
phase1_kernel(const float* __restrict__ self_vecs,
              const float* __restrict__ neigh_vecs)
{
    __shared__ float4 tile[KNBR * D / 4];   // 32 KB
    __shared__ float4 vn4[D / 4];
    __shared__ float  dots[KNBR];
    __shared__ float  warp_part[8];
    __shared__ float  s_selflogit;
    __shared__ float  sel_w[TOPK];
    __shared__ int    sel_i[TOPK];

    const int n    = blockIdx.x;
    const int t    = threadIdx.x;
    const int wid  = t >> 5;
    const int lane = t & 31;

    const float4* src = (const float4*)(neigh_vecs + (size_t)n * KNBR * D);
#pragma unroll
    for (int i = 0; i < 8; i++) tile[t + 256 * i] = src[t + 256 * i];
    if (t < D / 4) vn4[t] = ((const float4*)g_vn)[t];

    float sv = self_vecs[(size_t)n * D + t];
    {
        __nv_bfloat16 h = __float2bfloat16(sv);
        float lo = sv - __bfloat162float(h);
        g_Ah[(size_t)n * K2 + t] = h;
        g_Al[(size_t)n * K2 + t] = __float2bfloat16(lo);
    }
    float sp = sv * g_vs[t];
#pragma unroll
    for (int o = 16; o > 0; o >>= 1) sp += __shfl_down_sync(0xffffffffu, sp, o);
    if (lane == 0) warp_part[wid] = sp;
    __syncthreads();

#pragma unroll
    for (int r = 0; r < 4; r++) {
        int row = wid * 4 + r;
        float4 a0 = tile[row * 64 + lane];
        float4 a1 = tile[row * 64 + 32 + lane];
        float4 b0 = vn4[lane];
        float4 b1 = vn4[32 + lane];
        float p = a0.x * b0.x + a0.y * b0.y + a0.z * b0.z + a0.w * b0.w
                + a1.x * b1.x + a1.y * b1.y + a1.z * b1.z + a1.w * b1.w;
#pragma unroll
        for (int o = 16; o > 0; o >>= 1) p += __shfl_down_sync(0xffffffffu, p, o);
        if (lane == 0) dots[row] = p;
    }
    if (t == 0) {
        float s = 0.f;
#pragma unroll
        for (int i = 0; i < 8; i++) s += warp_part[i];
        s_selflogit = s;
    }
    __syncthreads();

    if (wid == 0) {
        float l  = fmaxf(dots[lane], 0.f);
        float l0 = fmaxf(s_selflogit, 0.f);
        float m = l;
#pragma unroll
        for (int o = 16; o > 0; o >>= 1) m = fmaxf(m, __shfl_xor_sync(0xffffffffu, m, o));
        m = fmaxf(m, l0);
        float e = expf(l - m);
        float ssum = e;
#pragma unroll
        for (int o = 16; o > 0; o >>= 1) ssum += __shfl_xor_sync(0xffffffffu, ssum, o);
        float denom = ssum + expf(l0 - m);
        float score = e / denom;

        int rank = 0;
#pragma unroll
        for (int j = 0; j < KNBR; j++) {
            float sj = __shfl_sync(0xffffffffu, score, j);
            rank += (sj > score) || (sj == score && j < lane);
        }
        if (rank < TOPK) { sel_w[rank] = score; sel_i[rank] = lane; }
    }
    __syncthreads();

    const float* ts = (const float*)tile;
    float acc = 0.f;
#pragma unroll
    for (int i = 0; i < TOPK; i++) acc += sel_w[i] * ts[sel_i[i] * D + t];
    __nv_bfloat16 h = __float2bfloat16(acc);
    float lo = acc - __bfloat162float(h);
    g_Ah[(size_t)n * K2 + D + t] = h;
    g_Al[(size_t)n * K2 + D + t] = __float2bfloat16(lo);
}

// ---------------------------------------------------------------------------
// Phase 2: out = relu(Ah·Bh + Ah·Bl + Al·Bh)
// BM=128, BN=64, BK=64, 8 warps (32x32 warp tiles), 3-stage cp.async pipeline.
// Iterations 0-7: A=Ah, compute vs Bh AND Bl (A frags reused).
// Iterations 8-15: A=Al, compute vs Bh only.
// ---------------------------------------------------------------------------
#define BK    64
#define RS    72                       // padded row stride (bf16 elems), 144 B
#define STG   36864                    // stage bytes: A 18432 + B0 9216 + B1 9216
#define AOF   0
#define B0OF  18432
#define B1OF  27648
#define GEMM_SMEM (3 * STG)            // 110592
#define NIT   16

__global__ void __launch_bounds__(256)
gemm_kernel(float* __restrict__ out, int nrows)
{
    extern __shared__ uint8_t sm[];

    const int t    = threadIdx.x;
    const int wid  = t >> 5;
    const int lane = t & 31;
    const int row0 = blockIdx.x * 128;
    const int col0 = blockIdx.y * 64;
    const int wm   = (wid >> 1) * 32;    // 0/32/64/96
    const int wn   = (wid & 1) * 32;     // 0/32

    float acc[2][4][4];
#pragma unroll
    for (int i = 0; i < 2; i++)
#pragma unroll
        for (int j = 0; j < 4; j++)
#pragma unroll
            for (int q = 0; q < 4; q++) acc[i][j][q] = 0.f;

    // prefetch iteration jt into stage st
    auto prefetch = [&](int jt, int st) {
        const int koff = (jt & 7) * BK;
        const bool dual = (jt < 8);
        const __nv_bfloat16* Ap = dual ? g_Ah : g_Al;
        uint8_t* stage = sm + st * STG;
        // A: 128 rows x 64 bf16 = 1024 x 16B chunks, 4 per thread
#pragma unroll
        for (int i = 0; i < 4; i++) {
            int idx = t + i * 256;
            int r = idx >> 3, c = idx & 7;
            uint32_t da = smem_u32(stage + AOF + r * 144 + c * 16);
            const void* sa = Ap + (size_t)(row0 + r) * K2 + koff + c * 8;
            asm volatile("cp.async.cg.shared.global [%0], [%1], 16;" :: "r"(da), "l"(sa));
        }
        // B0 (always Bh): 64 rows x 64 bf16 = 512 chunks, 2 per thread
#pragma unroll
        for (int i = 0; i < 2; i++) {
            int idx = t + i * 256;
            int r = idx >> 3, c = idx & 7;
            uint32_t db = smem_u32(stage + B0OF + r * 144 + c * 16);
            const void* sb = g_Bh + (size_t)(col0 + r) * K2 + koff + c * 8;
            asm volatile("cp.async.cg.shared.global [%0], [%1], 16;" :: "r"(db), "l"(sb));
        }
        // B1 (Bl) only in dual phase
        if (dual) {
#pragma unroll
            for (int i = 0; i < 2; i++) {
                int idx = t + i * 256;
                int r = idx >> 3, c = idx & 7;
                uint32_t db = smem_u32(stage + B1OF + r * 144 + c * 16);
                const void* sb = g_Bl + (size_t)(col0 + r) * K2 + koff + c * 8;
                asm volatile("cp.async.cg.shared.global [%0], [%1], 16;" :: "r"(db), "l"(sb));
            }
        }
        asm volatile("cp.async.commit_group;");
    };

    prefetch(0, 0);
    prefetch(1, 1);

#pragma unroll 1
    for (int it = 0; it < NIT; it++) {
        asm volatile("cp.async.wait_group 1;");
        __syncthreads();

        if (it + 2 < NIT) prefetch(it + 2, (it + 2) % 3);
        else asm volatile("cp.async.commit_group;");

        uint8_t* stage = sm + (it % 3) * STG;
        const bool dual = (it < 8);

#pragma unroll
        for (int s = 0; s < 4; s++) {            // four k16 steps in BK=64
            uint32_t a[2][4], b[4][2];
#pragma unroll
            for (int i = 0; i < 2; i++) {
                int rowA = wm + i * 16 + (lane & 15);
                int ka   = s * 16 + ((lane >> 4) << 3);
                uint32_t ad = smem_u32(stage + AOF + rowA * 144 + ka * 2);
                asm volatile("ldmatrix.sync.aligned.m8n8.x4.shared.b16 {%0,%1,%2,%3}, [%4];"
                             : "=r"(a[i][0]), "=r"(a[i][1]), "=r"(a[i][2]), "=r"(a[i][3])
                             : "r"(ad));
            }
#pragma unroll
            for (int j = 0; j < 4; j++) {
                int rowB = wn + j * 8 + (lane & 7);
                int kb   = s * 16 + (((lane >> 3) & 1) << 3);
                uint32_t bd = smem_u32(stage + B0OF + rowB * 144 + kb * 2);
                asm volatile("ldmatrix.sync.aligned.m8n8.x2.shared.b16 {%0,%1}, [%2];"
                             : "=r"(b[j][0]), "=r"(b[j][1]) : "r"(bd));
            }
#pragma unroll
            for (int i = 0; i < 2; i++)
#pragma unroll
                for (int j = 0; j < 4; j++) {
                    asm volatile(
                        "mma.sync.aligned.m16n8k16.row.col.f32.bf16.bf16.f32 "
                        "{%0,%1,%2,%3}, {%4,%5,%6,%7}, {%8,%9}, {%0,%1,%2,%3};"
                        : "+f"(acc[i][j][0]), "+f"(acc[i][j][1]),
                          "+f"(acc[i][j][2]), "+f"(acc[i][j][3])
                        : "r"(a[i][0]), "r"(a[i][1]), "r"(a[i][2]), "r"(a[i][3]),
                          "r"(b[j][0]), "r"(b[j][1]));
                }
            if (dual) {
#pragma unroll
                for (int j = 0; j < 4; j++) {
                    int rowB = wn + j * 8 + (lane & 7);
                    int kb   = s * 16 + (((lane >> 3) & 1) << 3);
                    uint32_t bd = smem_u32(stage + B1OF + rowB * 144 + kb * 2);
                    asm volatile("ldmatrix.sync.aligned.m8n8.x2.shared.b16 {%0,%1}, [%2];"
                                 : "=r"(b[j][0]), "=r"(b[j][1]) : "r"(bd));
                }
#pragma unroll
                for (int i = 0; i < 2; i++)
#pragma unroll
                    for (int j = 0; j < 4; j++) {
                        asm volatile(
                            "mma.sync.aligned.m16n8k16.row.col.f32.bf16.bf16.f32 "
                            "{%0,%1,%2,%3}, {%4,%5,%6,%7}, {%8,%9}, {%0,%1,%2,%3};"
                            : "+f"(acc[i][j][0]), "+f"(acc[i][j][1]),
                              "+f"(acc[i][j][2]), "+f"(acc[i][j][3])
                            : "r"(a[i][0]), "r"(a[i][1]), "r"(a[i][2]), "r"(a[i][3]),
                              "r"(b[j][0]), "r"(b[j][1]));
                    }
            }
        }
        __syncthreads();   // protect stage reuse by next-next prefetch
    }

    // epilogue: relu + store
#pragma unroll
    for (int i = 0; i < 2; i++) {
        int rA = row0 + wm + i * 16 + (lane >> 2);
        int rB = rA + 8;
#pragma unroll
        for (int j = 0; j < 4; j++) {
            int c = col0 + wn + j * 8 + (lane & 3) * 2;
            if (rA < nrows) {
                float2 v;
                v.x = fmaxf(acc[i][j][0], 0.f);
                v.y = fmaxf(acc[i][j][1], 0.f);
                *(float2*)&out[(size_t)rA * D + c] = v;
            }
            if (rB < nrows) {
                float2 v;
                v.x = fmaxf(acc[i][j][2], 0.f);
                v.y = fmaxf(acc[i][j][3], 0.f);
                *(float2*)&out[(size_t)rB * D + c] = v;
            }
        }
    }
}

// ---------------------------------------------------------------------------
extern "C" void kernel_launch(void* const* d_in, const int* in_sizes, int n_in,
                              void* d_out, int out_size)
{
    const float* self_vecs = (const float*)d_in[0];
    const float* neigh     = (const float*)d_in[1];
    const float* sw        = (const float*)d_in[2];
    const float* nw        = (const float*)d_in[3];
    const float* attn      = (const float*)d_in[4];
    float* out             = (float*)d_out;

    const int nrows = in_sizes[0] / D;   // 20000

    phase0_kernel<<<dim3(2, 8), 256>>>(sw, nw, attn);
    convB_kernel<<<(D * K2) / 256, 256>>>(sw, nw);
    phase1_kernel<<<nrows, 256>>>(self_vecs, neigh);

    cudaFuncSetAttribute(gemm_kernel, cudaFuncAttributeMaxDynamicSharedMemorySize, GEMM_SMEM);
    dim3 g2((nrows + 127) / 128, 4);
    gemm_kernel<<<g2, 256, GEMM_SMEM>>>(out, nrows);
}

// round 5
// speedup vs baseline: 2.1118x; 1.2740x over previous
#include <cuda_runtime.h>
#include <cuda_bf16.h>
#include <math.h>
#include <stdint.h>

#define D      256
#define KNBR   32
#define TOPK   16
#define MAXN   20096      // 157 * 128, padded
#define K2     512        // GEMM K = 2*D

// ---------------- scratch (__device__ globals; zero-init, no allocs) -------
__device__ __align__(128) __nv_bfloat16 g_Ah[(size_t)MAXN * K2];  // [row, 512] hi
__device__ __align__(128) __nv_bfloat16 g_Al[(size_t)MAXN * K2];  // [row, 512] lo
__device__ __align__(128) __nv_bfloat16 g_Bh[D * K2];             // [n, 512] hi (W^T)
__device__ __align__(128) __nv_bfloat16 g_Bl[D * K2];             // [n, 512] lo
__device__ float g_vs[D];
__device__ float g_vn[D];

__device__ __forceinline__ uint32_t smem_u32(const void* p) {
    uint32_t a;
    asm("{ .reg .u64 t; cvta.to.shared.u64 t, %1; cvt.u32.u64 %0, t; }" : "=r"(a) : "l"(p));
    return a;
}

// ---------------------------------------------------------------------------
// Phase 0: v = W @ a
// ---------------------------------------------------------------------------
__global__ void __launch_bounds__(256)
phase0_kernel(const float* __restrict__ sw, const float* __restrict__ nw,
              const float* __restrict__ attn)
{
    __shared__ float a[D];
    const int t = threadIdx.x, wid = t >> 5, lane = t & 31;
    a[t] = attn[t];
    __syncthreads();

    const float* w = (blockIdx.x == 0) ? sw : nw;
#pragma unroll
    for (int r = 0; r < 4; r++) {
        int row = blockIdx.y * 32 + wid * 4 + r;
        const float4* wr = (const float4*)(w + (size_t)row * D);
        float4 v0 = wr[lane], v1 = wr[lane + 32];
        float p = v0.x * a[4 * lane + 0] + v0.y * a[4 * lane + 1]
                + v0.z * a[4 * lane + 2] + v0.w * a[4 * lane + 3]
                + v1.x * a[128 + 4 * lane + 0] + v1.y * a[128 + 4 * lane + 1]
                + v1.z * a[128 + 4 * lane + 2] + v1.w * a[128 + 4 * lane + 3];
#pragma unroll
        for (int o = 16; o > 0; o >>= 1) p += __shfl_down_sync(0xffffffffu, p, o);
        if (lane == 0) { if (blockIdx.x == 0) g_vs[row] = p; else g_vn[row] = p; }
    }
}

// ---------------------------------------------------------------------------
// convert B = [Ws ; Wn]^T to bf16 hi/lo:  B[n, k] = W[k, n]
// ---------------------------------------------------------------------------
__global__ void __launch_bounds__(256)
convB_kernel(const float* __restrict__ ws, const float* __restrict__ nw)
{
    int idx = blockIdx.x * 256 + threadIdx.x;       // 0 .. 131071
    int n = idx & 255;
    int k = idx >> 8;                                // 0 .. 511
    float w = (k < D) ? ws[(size_t)k * D + n] : nw[(size_t)(k - D) * D + n];
    __nv_bfloat16 h = __float2bfloat16(w);
    float lo = w - __bfloat162float(h);
    g_Bh[(size_t)n * K2 + k] = h;
    g_Bl[(size_t)n * K2 + k] = __float2bfloat16(lo);
}

// ---------------------------------------------------------------------------
// Phase 1: per node — logits, softmax over 33, top-16, weighted neighbor sum.
// cp.async tile load overlapped with self-row processing.
// ---------------------------------------------------------------------------
__global__ void __launch_bounds__(256)
phase1_kernel(const float* __restrict__ self_vecs,
              const float* __restrict__ neigh_vecs)
{
    __shared__ float4 tile[KNBR * D / 4];   // 32 KB
    __shared__ float4 vn4[D / 4];
    __shared__ float  dots[KNBR];
    __shared__ float  warp_part[8];
    __shared__ float  s_selflogit;
    __shared__ float  sel_w[TOPK];
    __shared__ int    sel_i[TOPK];

    const int n    = blockIdx.x;
    const int t    = threadIdx.x;
    const int wid  = t >> 5;
    const int lane = t & 31;

    // async tile load: 8 x 16B per thread
    const float4* src = (const float4*)(neigh_vecs + (size_t)n * KNBR * D);
#pragma unroll
    for (int i = 0; i < 8; i++) {
        uint32_t dst = smem_u32(&tile[t + 256 * i]);
        asm volatile("cp.async.cg.shared.global [%0], [%1], 16;"
                     :: "r"(dst), "l"((const void*)(src + t + 256 * i)));
    }
    asm volatile("cp.async.commit_group;");

    if (t < D / 4) vn4[t] = ((const float4*)g_vn)[t];

    // overlap: self row element t (logit partial + bf16 hi/lo write, cols 0..255)
    float sv = self_vecs[(size_t)n * D + t];
    {
        __nv_bfloat16 h = __float2bfloat16(sv);
        float lo = sv - __bfloat162float(h);
        g_Ah[(size_t)n * K2 + t] = h;
        g_Al[(size_t)n * K2 + t] = __float2bfloat16(lo);
    }
    float sp = sv * g_vs[t];
#pragma unroll
    for (int o = 16; o > 0; o >>= 1) sp += __shfl_down_sync(0xffffffffu, sp, o);
    if (lane == 0) warp_part[wid] = sp;

    asm volatile("cp.async.wait_group 0;");
    __syncthreads();

#pragma unroll
    for (int r = 0; r < 4; r++) {
        int row = wid * 4 + r;
        float4 a0 = tile[row * 64 + lane];
        float4 a1 = tile[row * 64 + 32 + lane];
        float4 b0 = vn4[lane];
        float4 b1 = vn4[32 + lane];
        float p = a0.x * b0.x + a0.y * b0.y + a0.z * b0.z + a0.w * b0.w
                + a1.x * b1.x + a1.y * b1.y + a1.z * b1.z + a1.w * b1.w;
#pragma unroll
        for (int o = 16; o > 0; o >>= 1) p += __shfl_down_sync(0xffffffffu, p, o);
        if (lane == 0) dots[row] = p;
    }
    if (t == 0) {
        float s = 0.f;
#pragma unroll
        for (int i = 0; i < 8; i++) s += warp_part[i];
        s_selflogit = s;
    }
    __syncthreads();

    if (wid == 0) {
        float l  = fmaxf(dots[lane], 0.f);
        float l0 = fmaxf(s_selflogit, 0.f);
        float m = l;
#pragma unroll
        for (int o = 16; o > 0; o >>= 1) m = fmaxf(m, __shfl_xor_sync(0xffffffffu, m, o));
        m = fmaxf(m, l0);
        float e = expf(l - m);
        float ssum = e;
#pragma unroll
        for (int o = 16; o > 0; o >>= 1) ssum += __shfl_xor_sync(0xffffffffu, ssum, o);
        float denom = ssum + expf(l0 - m);
        float score = e / denom;

        int rank = 0;
#pragma unroll
        for (int j = 0; j < KNBR; j++) {
            float sj = __shfl_sync(0xffffffffu, score, j);
            rank += (sj > score) || (sj == score && j < lane);
        }
        if (rank < TOPK) { sel_w[rank] = score; sel_i[rank] = lane; }
    }
    __syncthreads();

    const float* ts = (const float*)tile;
    float acc = 0.f;
#pragma unroll
    for (int i = 0; i < TOPK; i++) acc += sel_w[i] * ts[sel_i[i] * D + t];
    __nv_bfloat16 h = __float2bfloat16(acc);
    float lo = acc - __bfloat162float(h);
    g_Ah[(size_t)n * K2 + D + t] = h;
    g_Al[(size_t)n * K2 + D + t] = __float2bfloat16(lo);
}

// ---------------------------------------------------------------------------
// Phase 2: out = relu(Ah·Bh + Ah·Bl + Al·Bh)
// BM=128, BN=64, BK=64, 8 warps (32x32 warp tiles), 3-stage cp.async pipeline.
// ldmatrix.x4 for both A and B (paired n8 tiles); hoisted addressing.
// ---------------------------------------------------------------------------
#define BK    64
#define STG   36864                    // stage bytes: A 18432 + B0 9216 + B1 9216
#define AOF   0
#define B0OF  18432
#define B1OF  27648
#define GEMM_SMEM (3 * STG)            // 110592
#define NIT   16

__global__ void __launch_bounds__(256)
gemm_kernel(float* __restrict__ out, int nrows)
{
    extern __shared__ uint8_t sm[];
    const uint32_t smb = smem_u32(sm);

    const int t    = threadIdx.x;
    const int wid  = t >> 5;
    const int lane = t & 31;
    const int row0 = blockIdx.x * 128;
    const int col0 = blockIdx.y * 64;
    const int wm   = (wid >> 1) * 32;    // 0/32/64/96
    const int wn   = (wid & 1) * 32;     // 0/32

    // precomputed lane fragment offsets (bytes within a stage)
    // A (x4): rowA = wm + i*16 + (lane&15); kbyte = ((lane>>4)<<3)*2
    uint32_t offA[2];
#pragma unroll
    for (int i = 0; i < 2; i++)
        offA[i] = AOF + (uint32_t)(wm + i * 16 + (lane & 15)) * 144
                + (uint32_t)(((lane >> 4) << 3) * 2);
    // B (x4): g = lane>>3; tile pair p: rows wn + (2p + (g>>1))*8 + (lane&7);
    //         kbyte = (g&1)*16
    uint32_t offB[2];
#pragma unroll
    for (int p = 0; p < 2; p++)
        offB[p] = (uint32_t)(wn + (2 * p + ((lane >> 3) >> 1)) * 8 + (lane & 7)) * 144
                + (uint32_t)(((lane >> 3) & 1) * 16);

    float acc[2][4][4];
#pragma unroll
    for (int i = 0; i < 2; i++)
#pragma unroll
        for (int j = 0; j < 4; j++)
#pragma unroll
            for (int q = 0; q < 4; q++) acc[i][j][q] = 0.f;

    auto prefetch = [&](int jt, int st) {
        const int koff = (jt & 7) * BK;
        const bool dual = (jt < 8);
        const __nv_bfloat16* Ap = dual ? g_Ah : g_Al;
        uint8_t* stage = sm + st * STG;
#pragma unroll
        for (int i = 0; i < 4; i++) {
            int idx = t + i * 256;
            int r = idx >> 3, c = idx & 7;
            uint32_t da = smem_u32(stage + AOF + r * 144 + c * 16);
            const void* sa = Ap + (size_t)(row0 + r) * K2 + koff + c * 8;
            asm volatile("cp.async.cg.shared.global [%0], [%1], 16;" :: "r"(da), "l"(sa));
        }
#pragma unroll
        for (int i = 0; i < 2; i++) {
            int idx = t + i * 256;
            int r = idx >> 3, c = idx & 7;
            uint32_t db = smem_u32(stage + B0OF + r * 144 + c * 16);
            const void* sb = g_Bh + (size_t)(col0 + r) * K2 + koff + c * 8;
            asm volatile("cp.async.cg.shared.global [%0], [%1], 16;" :: "r"(db), "l"(sb));
        }
        if (dual) {
#pragma unroll
            for (int i = 0; i < 2; i++) {
                int idx = t + i * 256;
                int r = idx >> 3, c = idx & 7;
                uint32_t db = smem_u32(stage + B1OF + r * 144 + c * 16);
                const void* sb = g_Bl + (size_t)(col0 + r) * K2 + koff + c * 8;
                asm volatile("cp.async.cg.shared.global [%0], [%1], 16;" :: "r"(db), "l"(sb));
            }
        }
        asm volatile("cp.async.commit_group;");
    };

    prefetch(0, 0);
    prefetch(1, 1);

#pragma unroll 1
    for (int it = 0; it < NIT; it++) {
        asm volatile("cp.async.wait_group 1;");
        __syncthreads();

        if (it + 2 < NIT) prefetch(it + 2, (it + 2) % 3);
        else asm volatile("cp.async.commit_group;");

        const uint32_t stage = smb + (uint32_t)((it % 3) * STG);
        const bool dual = (it < 8);

#pragma unroll
        for (int s = 0; s < 4; s++) {            // four k16 steps in BK=64
            const uint32_t sk = stage + (uint32_t)(s * 32);
            uint32_t a[2][4], b[4][2];
#pragma unroll
            for (int i = 0; i < 2; i++) {
                asm volatile("ldmatrix.sync.aligned.m8n8.x4.shared.b16 {%0,%1,%2,%3}, [%4];"
                             : "=r"(a[i][0]), "=r"(a[i][1]), "=r"(a[i][2]), "=r"(a[i][3])
                             : "r"(sk + offA[i]));
            }
#pragma unroll
            for (int p = 0; p < 2; p++) {
                asm volatile("ldmatrix.sync.aligned.m8n8.x4.shared.b16 {%0,%1,%2,%3}, [%4];"
                             : "=r"(b[2 * p][0]), "=r"(b[2 * p][1]),
                               "=r"(b[2 * p + 1][0]), "=r"(b[2 * p + 1][1])
                             : "r"(sk + B0OF + offB[p]));
            }
#pragma unroll
            for (int i = 0; i < 2; i++)
#pragma unroll
                for (int j = 0; j < 4; j++) {
                    asm volatile(
                        "mma.sync.aligned.m16n8k16.row.col.f32.bf16.bf16.f32 "
                        "{%0,%1,%2,%3}, {%4,%5,%6,%7}, {%8,%9}, {%0,%1,%2,%3};"
                        : "+f"(acc[i][j][0]), "+f"(acc[i][j][1]),
                          "+f"(acc[i][j][2]), "+f"(acc[i][j][3])
                        : "r"(a[i][0]), "r"(a[i][1]), "r"(a[i][2]), "r"(a[i][3]),
                          "r"(b[j][0]), "r"(b[j][1]));
                }
            if (dual) {
#pragma unroll
                for (int p = 0; p < 2; p++) {
                    asm volatile("ldmatrix.sync.aligned.m8n8.x4.shared.b16 {%0,%1,%2,%3}, [%4];"
                                 : "=r"(b[2 * p][0]), "=r"(b[2 * p][1]),
                                   "=r"(b[2 * p + 1][0]), "=r"(b[2 * p + 1][1])
                                 : "r"(sk + B1OF + offB[p]));
                }
#pragma unroll
                for (int i = 0; i < 2; i++)
#pragma unroll
                    for (int j = 0; j < 4; j++) {
                        asm volatile(
                            "mma.sync.aligned.m16n8k16.row.col.f32.bf16.bf16.f32 "
                            "{%0,%1,%2,%3}, {%4,%5,%6,%7}, {%8,%9}, {%0,%1,%2,%3};"
                            : "+f"(acc[i][j][0]), "+f"(acc[i][j][1]),
                              "+f"(acc[i][j][2]), "+f"(acc[i][j][3])
                            : "r"(a[i][0]), "r"(a[i][1]), "r"(a[i][2]), "r"(a[i][3]),
                              "r"(b[j][0]), "r"(b[j][1]));
                    }
            }
        }
        __syncthreads();   // protect stage reuse by next-next prefetch
    }

    // epilogue: relu + store
#pragma unroll
    for (int i = 0; i < 2; i++) {
        int rA = row0 + wm + i * 16 + (lane >> 2);
        int rB = rA + 8;
#pragma unroll
        for (int j = 0; j < 4; j++) {
            int c = col0 + wn + j * 8 + (lane & 3) * 2;
            if (rA < nrows) {
                float2 v;
                v.x = fmaxf(acc[i][j][0], 0.f);
                v.y = fmaxf(acc[i][j][1], 0.f);
                *(float2*)&out[(size_t)rA * D + c] = v;
            }
            if (rB < nrows) {
                float2 v;
                v.x = fmaxf(acc[i][j][2], 0.f);
                v.y = fmaxf(acc[i][j][3], 0.f);
                *(float2*)&out[(size_t)rB * D + c] = v;
            }
        }
    }
}

// ---------------------------------------------------------------------------
extern "C" void kernel_launch(void* const* d_in, const int* in_sizes, int n_in,
                              void* d_out, int out_size)
{
    const float* self_vecs = (const float*)d_in[0];
    const float* neigh     = (const float*)d_in[1];
    const float* sw        = (const float*)d_in[2];
    const float* nw        = (const float*)d_in[3];
    const float* attn      = (const float*)d_in[4];
    float* out             = (float*)d_out;

    const int nrows = in_sizes[0] / D;   // 20000

    phase0_kernel<<<dim3(2, 8), 256>>>(sw, nw, attn);
    convB_kernel<<<(D * K2) / 256, 256>>>(sw, nw);
    phase1_kernel<<<nrows, 256>>>(self_vecs, neigh);

    cudaFuncSetAttribute(gemm_kernel, cudaFuncAttributeMaxDynamicSharedMemorySize, GEMM_SMEM);
    dim3 g2((nrows + 127) / 128, 4);
    gemm_kernel<<<g2, 256, GEMM_SMEM>>>(out, nrows);
}

// round 6
// speedup vs baseline: 2.3424x; 1.1092x over previous
#include <cuda_runtime.h>
#include <cuda_fp16.h>
#include <math.h>
#include <stdint.h>

#define D      256
#define KNBR   32
#define TOPK   16
#define MAXN   20096      // 157 * 128, padded
#define K2     512        // GEMM K = 2*D

// ---------------- scratch (__device__ globals; zero-init, no allocs) -------
__device__ __align__(128) __half g_Ah[(size_t)MAXN * K2];  // [row, 512] fp16 hi
__device__ __align__(128) __half g_Al[(size_t)MAXN * K2];  // [row, 512] fp16 residual
__device__ __align__(128) __half g_Bh[D * K2];             // [n, 512] fp16 (W^T)
__device__ float g_vs[D];
__device__ float g_vn[D];

__device__ __forceinline__ uint32_t smem_u32(const void* p) {
    uint32_t a;
    asm("{ .reg .u64 t; cvta.to.shared.u64 t, %1; cvt.u32.u64 %0, t; }" : "=r"(a) : "l"(p));
    return a;
}

// ---------------------------------------------------------------------------
// Phase 0: v = W @ a
// ---------------------------------------------------------------------------
__global__ void __launch_bounds__(256)
phase0_kernel(const float* __restrict__ sw, const float* __restrict__ nw,
              const float* __restrict__ attn)
{
    __shared__ float a[D];
    const int t = threadIdx.x, wid = t >> 5, lane = t & 31;
    a[t] = attn[t];
    __syncthreads();

    const float* w = (blockIdx.x == 0) ? sw : nw;
#pragma unroll
    for (int r = 0; r < 4; r++) {
        int row = blockIdx.y * 32 + wid * 4 + r;
        const float4* wr = (const float4*)(w + (size_t)row * D);
        float4 v0 = wr[lane], v1 = wr[lane + 32];
        float p = v0.x * a[4 * lane + 0] + v0.y * a[4 * lane + 1]
                + v0.z * a[4 * lane + 2] + v0.w * a[4 * lane + 3]
                + v1.x * a[128 + 4 * lane + 0] + v1.y * a[128 + 4 * lane + 1]
                + v1.z * a[128 + 4 * lane + 2] + v1.w * a[128 + 4 * lane + 3];
#pragma unroll
        for (int o = 16; o > 0; o >>= 1) p += __shfl_down_sync(0xffffffffu, p, o);
        if (lane == 0) { if (blockIdx.x == 0) g_vs[row] = p; else g_vn[row] = p; }
    }
}

// ---------------------------------------------------------------------------
// convert B = [Ws ; Wn]^T to fp16:  B[n, k] = W[k, n]
// ---------------------------------------------------------------------------
__global__ void __launch_bounds__(256)
convB_kernel(const float* __restrict__ ws, const float* __restrict__ nw)
{
    int idx = blockIdx.x * 256 + threadIdx.x;       // 0 .. 131071
    int n = idx & 255;
    int k = idx >> 8;                                // 0 .. 511
    float w = (k < D) ? ws[(size_t)k * D + n] : nw[(size_t)(k - D) * D + n];
    g_Bh[(size_t)n * K2 + k] = __float2half_rn(w);
}

// ---------------------------------------------------------------------------
// Phase 1: per node — logits, softmax over 33, top-16, weighted neighbor sum.
// cp.async tile load overlapped with self-row processing. Writes A fp16 hi/lo.
// ---------------------------------------------------------------------------
__global__ void __launch_bounds__(256)
phase1_kernel(const float* __restrict__ self_vecs,
              const float* __restrict__ neigh_vecs)
{
    __shared__ float4 tile[KNBR * D / 4];   // 32 KB
    __shared__ float4 vn4[D / 4];
    __shared__ float  dots[KNBR];
    __shared__ float  warp_part[8];
    __shared__ float  s_selflogit;
    __shared__ float  sel_w[TOPK];
    __shared__ int    sel_i[TOPK];

    const int n    = blockIdx.x;
    const int t    = threadIdx.x;
    const int wid  = t >> 5;
    const int lane = t & 31;

    const float4* src = (const float4*)(neigh_vecs + (size_t)n * KNBR * D);
#pragma unroll
    for (int i = 0; i < 8; i++) {
        uint32_t dst = smem_u32(&tile[t + 256 * i]);
        asm volatile("cp.async.cg.shared.global [%0], [%1], 16;"
                     :: "r"(dst), "l"((const void*)(src + t + 256 * i)));
    }
    asm volatile("cp.async.commit_group;");

    if (t < D / 4) vn4[t] = ((const float4*)g_vn)[t];

    // overlap: self row element t (logit partial + fp16 hi/lo write, cols 0..255)
    float sv = self_vecs[(size_t)n * D + t];
    {
        __half h = __float2half_rn(sv);
        float lo = sv - __half2float(h);
        g_Ah[(size_t)n * K2 + t] = h;
        g_Al[(size_t)n * K2 + t] = __float2half_rn(lo);
    }
    float sp = sv * g_vs[t];
#pragma unroll
    for (int o = 16; o > 0; o >>= 1) sp += __shfl_down_sync(0xffffffffu, sp, o);
    if (lane == 0) warp_part[wid] = sp;

    asm volatile("cp.async.wait_group 0;");
    __syncthreads();

#pragma unroll
    for (int r = 0; r < 4; r++) {
        int row = wid * 4 + r;
        float4 a0 = tile[row * 64 + lane];
        float4 a1 = tile[row * 64 + 32 + lane];
        float4 b0 = vn4[lane];
        float4 b1 = vn4[32 + lane];
        float p = a0.x * b0.x + a0.y * b0.y + a0.z * b0.z + a0.w * b0.w
                + a1.x * b1.x + a1.y * b1.y + a1.z * b1.z + a1.w * b1.w;
#pragma unroll
        for (int o = 16; o > 0; o >>= 1) p += __shfl_down_sync(0xffffffffu, p, o);
        if (lane == 0) dots[row] = p;
    }
    if (t == 0) {
        float s = 0.f;
#pragma unroll
        for (int i = 0; i < 8; i++) s += warp_part[i];
        s_selflogit = s;
    }
    __syncthreads();

    if (wid == 0) {
        float l  = fmaxf(dots[lane], 0.f);
        float l0 = fmaxf(s_selflogit, 0.f);
        float m = l;
#pragma unroll
        for (int o = 16; o > 0; o >>= 1) m = fmaxf(m, __shfl_xor_sync(0xffffffffu, m, o));
        m = fmaxf(m, l0);
        float e = expf(l - m);
        float ssum = e;
#pragma unroll
        for (int o = 16; o > 0; o >>= 1) ssum += __shfl_xor_sync(0xffffffffu, ssum, o);
        float denom = ssum + expf(l0 - m);
        float score = e / denom;

        int rank = 0;
#pragma unroll
        for (int j = 0; j < KNBR; j++) {
            float sj = __shfl_sync(0xffffffffu, score, j);
            rank += (sj > score) || (sj == score && j < lane);
        }
        if (rank < TOPK) { sel_w[rank] = score; sel_i[rank] = lane; }
    }
    __syncthreads();

    const float* ts = (const float*)tile;
    float acc = 0.f;
#pragma unroll
    for (int i = 0; i < TOPK; i++) acc += sel_w[i] * ts[sel_i[i] * D + t];
    __half h = __float2half_rn(acc);
    float lo = acc - __half2float(h);
    g_Ah[(size_t)n * K2 + D + t] = h;
    g_Al[(size_t)n * K2 + D + t] = __float2half_rn(lo);
}

// ---------------------------------------------------------------------------
// Phase 2: out = relu(Ah·Bh + Al·Bh)  (fp16 2-pass, fp32 accum)
// BM=128, BN=64, BK=64, 8 warps (32x32 warp tiles), 4-stage cp.async pipeline,
// single __syncthreads per iteration.
// Iterations 0-7: A=Ah; 8-15: A=Al.
// ---------------------------------------------------------------------------
#define BK    64
#define STG   27648                    // stage bytes: A 18432 + B 9216
#define AOF   0
#define B0OF  18432
#define GEMM_SMEM (4 * STG)            // 110592
#define NIT   16

__global__ void __launch_bounds__(256)
gemm_kernel(float* __restrict__ out, int nrows)
{
    extern __shared__ uint8_t sm[];
    const uint32_t smb = smem_u32(sm);

    const int t    = threadIdx.x;
    const int wid  = t >> 5;
    const int lane = t & 31;
    const int row0 = blockIdx.x * 128;
    const int col0 = blockIdx.y * 64;
    const int wm   = (wid >> 1) * 32;    // 0/32/64/96
    const int wn   = (wid & 1) * 32;     // 0/32

    // precomputed lane fragment offsets (bytes within a stage)
    uint32_t offA[2];
#pragma unroll
    for (int i = 0; i < 2; i++)
        offA[i] = AOF + (uint32_t)(wm + i * 16 + (lane & 15)) * 144
                + (uint32_t)(((lane >> 4) << 3) * 2);
    uint32_t offB[2];
#pragma unroll
    for (int p = 0; p < 2; p++)
        offB[p] = (uint32_t)(wn + (2 * p + ((lane >> 3) >> 1)) * 8 + (lane & 7)) * 144
                + (uint32_t)(((lane >> 3) & 1) * 16);

    float acc[2][4][4];
#pragma unroll
    for (int i = 0; i < 2; i++)
#pragma unroll
        for (int j = 0; j < 4; j++)
#pragma unroll
            for (int q = 0; q < 4; q++) acc[i][j][q] = 0.f;

    auto prefetch = [&](int jt, int st) {
        const int koff = (jt & 7) * BK;
        const __half* Ap = (jt < 8) ? g_Ah : g_Al;
        uint8_t* stage = sm + st * STG;
#pragma unroll
        for (int i = 0; i < 4; i++) {
            int idx = t + i * 256;
            int r = idx >> 3, c = idx & 7;
            uint32_t da = smem_u32(stage + AOF + r * 144 + c * 16);
            const void* sa = Ap + (size_t)(row0 + r) * K2 + koff + c * 8;
            asm volatile("cp.async.cg.shared.global [%0], [%1], 16;" :: "r"(da), "l"(sa));
        }
#pragma unroll
        for (int i = 0; i < 2; i++) {
            int idx = t + i * 256;
            int r = idx >> 3, c = idx & 7;
            uint32_t db = smem_u32(stage + B0OF + r * 144 + c * 16);
            const void* sb = g_Bh + (size_t)(col0 + r) * K2 + koff + c * 8;
            asm volatile("cp.async.cg.shared.global [%0], [%1], 16;" :: "r"(db), "l"(sb));
        }
        asm volatile("cp.async.commit_group;");
    };

    prefetch(0, 0);
    prefetch(1, 1);
    prefetch(2, 2);

#pragma unroll 1
    for (int it = 0; it < NIT; it++) {
        asm volatile("cp.async.wait_group 2;");
        __syncthreads();                        // orders it-1 compute before stage reuse

        if (it + 3 < NIT) prefetch(it + 3, (it + 3) & 3);
        else asm volatile("cp.async.commit_group;");

        const uint32_t stage = smb + (uint32_t)((it & 3) * STG);

#pragma unroll
        for (int s = 0; s < 4; s++) {            // four k16 steps in BK=64
            const uint32_t sk = stage + (uint32_t)(s * 32);
            uint32_t a[2][4], b[4][2];
#pragma unroll
            for (int i = 0; i < 2; i++) {
                asm volatile("ldmatrix.sync.aligned.m8n8.x4.shared.b16 {%0,%1,%2,%3}, [%4];"
                             : "=r"(a[i][0]), "=r"(a[i][1]), "=r"(a[i][2]), "=r"(a[i][3])
                             : "r"(sk + offA[i]));
            }
#pragma unroll
            for (int p = 0; p < 2; p++) {
                asm volatile("ldmatrix.sync.aligned.m8n8.x4.shared.b16 {%0,%1,%2,%3}, [%4];"
                             : "=r"(b[2 * p][0]), "=r"(b[2 * p][1]),
                               "=r"(b[2 * p + 1][0]), "=r"(b[2 * p + 1][1])
                             : "r"(sk + B0OF + offB[p]));
            }
#pragma unroll
            for (int i = 0; i < 2; i++)
#pragma unroll
                for (int j = 0; j < 4; j++) {
                    asm volatile(
                        "mma.sync.aligned.m16n8k16.row.col.f32.f16.f16.f32 "
                        "{%0,%1,%2,%3}, {%4,%5,%6,%7}, {%8,%9}, {%0,%1,%2,%3};"
                        : "+f"(acc[i][j][0]), "+f"(acc[i][j][1]),
                          "+f"(acc[i][j][2]), "+f"(acc[i][j][3])
                        : "r"(a[i][0]), "r"(a[i][1]), "r"(a[i][2]), "r"(a[i][3]),
                          "r"(b[j][0]), "r"(b[j][1]));
                }
        }
    }

    __syncthreads();

    // epilogue: relu + store
#pragma unroll
    for (int i = 0; i < 2; i++) {
        int rA = row0 + wm + i * 16 + (lane >> 2);
        int rB = rA + 8;
#pragma unroll
        for (int j = 0; j < 4; j++) {
            int c = col0 + wn + j * 8 + (lane & 3) * 2;
            if (rA < nrows) {
                float2 v;
                v.x = fmaxf(acc[i][j][0], 0.f);
                v.y = fmaxf(acc[i][j][1], 0.f);
                *(float2*)&out[(size_t)rA * D + c] = v;
            }
            if (rB < nrows) {
                float2 v;
                v.x = fmaxf(acc[i][j][2], 0.f);
                v.y = fmaxf(acc[i][j][3], 0.f);
                *(float2*)&out[(size_t)rB * D + c] = v;
            }
        }
    }
}

// ---------------------------------------------------------------------------
extern "C" void kernel_launch(void* const* d_in, const int* in_sizes, int n_in,
                              void* d_out, int out_size)
{
    const float* self_vecs = (const float*)d_in[0];
    const float* neigh     = (const float*)d_in[1];
    const float* sw        = (const float*)d_in[2];
    const float* nw        = (const float*)d_in[3];
    const float* attn      = (const float*)d_in[4];
    float* out             = (float*)d_out;

    const int nrows = in_sizes[0] / D;   // 20000

    phase0_kernel<<<dim3(2, 8), 256>>>(sw, nw, attn);
    convB_kernel<<<(D * K2) / 256, 256>>>(sw, nw);
    phase1_kernel<<<nrows, 256>>>(self_vecs, neigh);

    cudaFuncSetAttribute(gemm_kernel, cudaFuncAttributeMaxDynamicSharedMemorySize, GEMM_SMEM);
    dim3 g2((nrows + 127) / 128, 4);
    gemm_kernel<<<g2, 256, GEMM_SMEM>>>(out, nrows);
}

// round 7
// speedup vs baseline: 2.7780x; 1.1860x over previous
#include <cuda_runtime.h>
#include <cuda_fp16.h>
#include <math.h>
#include <stdint.h>

#define D      256
#define KNBR   32
#define TOPK   16
#define MAXN   20096      // 157 * 128, padded
#define K2     512        // GEMM K = 2*D

// ---------------- scratch (__device__ globals; zero-init, no allocs) -------
__device__ __align__(128) __half g_Ah[(size_t)MAXN * K2];  // [row, 512] fp16
__device__ __align__(128) __half g_Bh[D * K2];             // [n, 512] fp16 (W^T)
__device__ float g_vs[D];
__device__ float g_vn[D];

__device__ __forceinline__ uint32_t smem_u32(const void* p) {
    uint32_t a;
    asm("{ .reg .u64 t; cvta.to.shared.u64 t, %1; cvt.u32.u64 %0, t; }" : "=r"(a) : "l"(p));
    return a;
}

// ---------------------------------------------------------------------------
// Phase 0 (merged): blocks 0..15 -> v = W @ a GEMV rows; blocks 16.. -> convB
// ---------------------------------------------------------------------------
__global__ void __launch_bounds__(256)
prep_kernel(const float* __restrict__ sw, const float* __restrict__ nw,
            const float* __restrict__ attn)
{
    const int b = blockIdx.x;
    const int t = threadIdx.x;

    if (b < 16) {
        // GEMV part: b&1 selects matrix, b>>1 selects 32-row group
        __shared__ float a[D];
        const int wid = t >> 5, lane = t & 31;
        a[t] = attn[t];
        __syncthreads();

        const float* w = ((b & 1) == 0) ? sw : nw;
#pragma unroll
        for (int r = 0; r < 4; r++) {
            int row = (b >> 1) * 32 + wid * 4 + r;
            const float4* wr = (const float4*)(w + (size_t)row * D);
            float4 v0 = wr[lane], v1 = wr[lane + 32];
            float p = v0.x * a[4 * lane + 0] + v0.y * a[4 * lane + 1]
                    + v0.z * a[4 * lane + 2] + v0.w * a[4 * lane + 3]
                    + v1.x * a[128 + 4 * lane + 0] + v1.y * a[128 + 4 * lane + 1]
                    + v1.z * a[128 + 4 * lane + 2] + v1.w * a[128 + 4 * lane + 3];
#pragma unroll
            for (int o = 16; o > 0; o >>= 1) p += __shfl_down_sync(0xffffffffu, p, o);
            if (lane == 0) { if ((b & 1) == 0) g_vs[row] = p; else g_vn[row] = p; }
        }
    } else {
        // convB part: B[n, k] = W[k, n] as fp16
        int idx = (b - 16) * 256 + t;                // 0 .. 131071
        int n = idx & 255;
        int k = idx >> 8;                            // 0 .. 511
        float w = (k < D) ? sw[(size_t)k * D + n] : nw[(size_t)(k - D) * D + n];
        g_Bh[(size_t)n * K2 + k] = __float2half_rn(w);
    }
}

// ---------------------------------------------------------------------------
// Phase 1: per node — logits, softmax over 33, top-16, weighted neighbor sum.
// cp.async tile load overlapped with self-row processing. Writes A fp16.
// ---------------------------------------------------------------------------
__global__ void __launch_bounds__(256)
phase1_kernel(const float* __restrict__ self_vecs,
              const float* __restrict__ neigh_vecs)
{
    __shared__ float4 tile[KNBR * D / 4];   // 32 KB
    __shared__ float4 vn4[D / 4];
    __shared__ float  dots[KNBR];
    __shared__ float  warp_part[8];
    __shared__ float  s_selflogit;
    __shared__ float  sel_w[TOPK];
    __shared__ int    sel_i[TOPK];

    const int n    = blockIdx.x;
    const int t    = threadIdx.x;
    const int wid  = t >> 5;
    const int lane = t & 31;

    const float4* src = (const float4*)(neigh_vecs + (size_t)n * KNBR * D);
#pragma unroll
    for (int i = 0; i < 8; i++) {
        uint32_t dst = smem_u32(&tile[t + 256 * i]);
        asm volatile("cp.async.cg.shared.global [%0], [%1], 16;"
                     :: "r"(dst), "l"((const void*)(src + t + 256 * i)));
    }
    asm volatile("cp.async.commit_group;");

    if (t < D / 4) vn4[t] = ((const float4*)g_vn)[t];

    // overlap: self row element t (logit partial + fp16 write, cols 0..255)
    float sv = self_vecs[(size_t)n * D + t];
    g_Ah[(size_t)n * K2 + t] = __float2half_rn(sv);
    float sp = sv * g_vs[t];
#pragma unroll
    for (int o = 16; o > 0; o >>= 1) sp += __shfl_down_sync(0xffffffffu, sp, o);
    if (lane == 0) warp_part[wid] = sp;

    asm volatile("cp.async.wait_group 0;");
    __syncthreads();

#pragma unroll
    for (int r = 0; r < 4; r++) {
        int row = wid * 4 + r;
        float4 a0 = tile[row * 64 + lane];
        float4 a1 = tile[row * 64 + 32 + lane];
        float4 b0 = vn4[lane];
        float4 b1 = vn4[32 + lane];
        float p = a0.x * b0.x + a0.y * b0.y + a0.z * b0.z + a0.w * b0.w
                + a1.x * b1.x + a1.y * b1.y + a1.z * b1.z + a1.w * b1.w;
#pragma unroll
        for (int o = 16; o > 0; o >>= 1) p += __shfl_down_sync(0xffffffffu, p, o);
        if (lane == 0) dots[row] = p;
    }
    if (t == 0) {
        float s = 0.f;
#pragma unroll
        for (int i = 0; i < 8; i++) s += warp_part[i];
        s_selflogit = s;
    }
    __syncthreads();

    if (wid == 0) {
        float l  = fmaxf(dots[lane], 0.f);
        float l0 = fmaxf(s_selflogit, 0.f);
        float m = l;
#pragma unroll
        for (int o = 16; o > 0; o >>= 1) m = fmaxf(m, __shfl_xor_sync(0xffffffffu, m, o));
        m = fmaxf(m, l0);
        float e = expf(l - m);
        float ssum = e;
#pragma unroll
        for (int o = 16; o > 0; o >>= 1) ssum += __shfl_xor_sync(0xffffffffu, ssum, o);
        float denom = ssum + expf(l0 - m);
        float score = e / denom;

        int rank = 0;
#pragma unroll
        for (int j = 0; j < KNBR; j++) {
            float sj = __shfl_sync(0xffffffffu, score, j);
            rank += (sj > score) || (sj == score && j < lane);
        }
        if (rank < TOPK) { sel_w[rank] = score; sel_i[rank] = lane; }
    }
    __syncthreads();

    const float* ts = (const float*)tile;
    float acc = 0.f;
#pragma unroll
    for (int i = 0; i < TOPK; i++) acc += sel_w[i] * ts[sel_i[i] * D + t];
    g_Ah[(size_t)n * K2 + D + t] = __float2half_rn(acc);
}

// ---------------------------------------------------------------------------
// Phase 2: out = relu(A @ B^T), single-pass fp16, fp32 accum.
// BM=128, BN=64, BK=64, 8 warps (32x32 warp tiles), 4-stage cp.async pipeline,
// single __syncthreads per iteration.
// ---------------------------------------------------------------------------
#define BK    64
#define STG   27648                    // stage bytes: A 18432 + B 9216
#define AOF   0
#define B0OF  18432
#define GEMM_SMEM (4 * STG)            // 110592
#define NIT   8

__global__ void __launch_bounds__(256)
gemm_kernel(float* __restrict__ out, int nrows)
{
    extern __shared__ uint8_t sm[];
    const uint32_t smb = smem_u32(sm);

    const int t    = threadIdx.x;
    const int wid  = t >> 5;
    const int lane = t & 31;
    const int row0 = blockIdx.x * 128;
    const int col0 = blockIdx.y * 64;
    const int wm   = (wid >> 1) * 32;    // 0/32/64/96
    const int wn   = (wid & 1) * 32;     // 0/32

    uint32_t offA[2];
#pragma unroll
    for (int i = 0; i < 2; i++)
        offA[i] = AOF + (uint32_t)(wm + i * 16 + (lane & 15)) * 144
                + (uint32_t)(((lane >> 4) << 3) * 2);
    uint32_t offB[2];
#pragma unroll
    for (int p = 0; p < 2; p++)
        offB[p] = (uint32_t)(wn + (2 * p + ((lane >> 3) >> 1)) * 8 + (lane & 7)) * 144
                + (uint32_t)(((lane >> 3) & 1) * 16);

    float acc[2][4][4];
#pragma unroll
    for (int i = 0; i < 2; i++)
#pragma unroll
        for (int j = 0; j < 4; j++)
#pragma unroll
            for (int q = 0; q < 4; q++) acc[i][j][q] = 0.f;

    auto prefetch = [&](int jt, int st) {
        const int koff = jt * BK;
        uint8_t* stage = sm + st * STG;
#pragma unroll
        for (int i = 0; i < 4; i++) {
            int idx = t + i * 256;
            int r = idx >> 3, c = idx & 7;
            uint32_t da = smem_u32(stage + AOF + r * 144 + c * 16);
            const void* sa = g_Ah + (size_t)(row0 + r) * K2 + koff + c * 8;
            asm volatile("cp.async.cg.shared.global [%0], [%1], 16;" :: "r"(da), "l"(sa));
        }
#pragma unroll
        for (int i = 0; i < 2; i++) {
            int idx = t + i * 256;
            int r = idx >> 3, c = idx & 7;
            uint32_t db = smem_u32(stage + B0OF + r * 144 + c * 16);
            const void* sb = g_Bh + (size_t)(col0 + r) * K2 + koff + c * 8;
            asm volatile("cp.async.cg.shared.global [%0], [%1], 16;" :: "r"(db), "l"(sb));
        }
        asm volatile("cp.async.commit_group;");
    };

    prefetch(0, 0);
    prefetch(1, 1);
    prefetch(2, 2);

#pragma unroll 1
    for (int it = 0; it < NIT; it++) {
        asm volatile("cp.async.wait_group 2;");
        __syncthreads();                        // orders it-1 compute before stage reuse

        if (it + 3 < NIT) prefetch(it + 3, (it + 3) & 3);
        else asm volatile("cp.async.commit_group;");

        const uint32_t stage = smb + (uint32_t)((it & 3) * STG);

#pragma unroll
        for (int s = 0; s < 4; s++) {            // four k16 steps in BK=64
            const uint32_t sk = stage + (uint32_t)(s * 32);
            uint32_t a[2][4], b[4][2];
#pragma unroll
            for (int i = 0; i < 2; i++) {
                asm volatile("ldmatrix.sync.aligned.m8n8.x4.shared.b16 {%0,%1,%2,%3}, [%4];"
                             : "=r"(a[i][0]), "=r"(a[i][1]), "=r"(a[i][2]), "=r"(a[i][3])
                             : "r"(sk + offA[i]));
            }
#pragma unroll
            for (int p = 0; p < 2; p++) {
                asm volatile("ldmatrix.sync.aligned.m8n8.x4.shared.b16 {%0,%1,%2,%3}, [%4];"
                             : "=r"(b[2 * p][0]), "=r"(b[2 * p][1]),
                               "=r"(b[2 * p + 1][0]), "=r"(b[2 * p + 1][1])
                             : "r"(sk + B0OF + offB[p]));
            }
#pragma unroll
            for (int i = 0; i < 2; i++)
#pragma unroll
                for (int j = 0; j < 4; j++) {
                    asm volatile(
                        "mma.sync.aligned.m16n8k16.row.col.f32.f16.f16.f32 "
                        "{%0,%1,%2,%3}, {%4,%5,%6,%7}, {%8,%9}, {%0,%1,%2,%3};"
                        : "+f"(acc[i][j][0]), "+f"(acc[i][j][1]),
                          "+f"(acc[i][j][2]), "+f"(acc[i][j][3])
                        : "r"(a[i][0]), "r"(a[i][1]), "r"(a[i][2]), "r"(a[i][3]),
                          "r"(b[j][0]), "r"(b[j][1]));
                }
        }
    }

    __syncthreads();

    // epilogue: relu + store
#pragma unroll
    for (int i = 0; i < 2; i++) {
        int rA = row0 + wm + i * 16 + (lane >> 2);
        int rB = rA + 8;
#pragma unroll
        for (int j = 0; j < 4; j++) {
            int c = col0 + wn + j * 8 + (lane & 3) * 2;
            if (rA < nrows) {
                float2 v;
                v.x = fmaxf(acc[i][j][0], 0.f);
                v.y = fmaxf(acc[i][j][1], 0.f);
                *(float2*)&out[(size_t)rA * D + c] = v;
            }
            if (rB < nrows) {
                float2 v;
                v.x = fmaxf(acc[i][j][2], 0.f);
                v.y = fmaxf(acc[i][j][3], 0.f);
                *(float2*)&out[(size_t)rB * D + c] = v;
            }
        }
    }
}

// ---------------------------------------------------------------------------
extern "C" void kernel_launch(void* const* d_in, const int* in_sizes, int n_in,
                              void* d_out, int out_size)
{
    const float* self_vecs = (const float*)d_in[0];
    const float* neigh     = (const float*)d_in[1];
    const float* sw        = (const float*)d_in[2];
    const float* nw        = (const float*)d_in[3];
    const float* attn      = (const float*)d_in[4];
    float* out             = (float*)d_out;

    const int nrows = in_sizes[0] / D;   // 20000

    prep_kernel<<<16 + (D * K2) / 256, 256>>>(sw, nw, attn);
    phase1_kernel<<<nrows, 256>>>(self_vecs, neigh);

    cudaFuncSetAttribute(gemm_kernel, cudaFuncAttributeMaxDynamicSharedMemorySize, GEMM_SMEM);
    dim3 g2((nrows + 127) / 128, 4);
    gemm_kernel<<<g2, 256, GEMM_SMEM>>>(out, nrows);
}